// round 11
// baseline (speedup 1.0000x reference)
#include <cuda_runtime.h>
#include <cstdint>
#include <math.h>

#define Bb 2
#define Ss 2048
#define Dd 1024
#define Hh 16
#define HD 64
#define Mm (Bb*Ss)

// Scratch (allocation-free: __device__ globals)
__device__ float g_q[Bb*Hh*Ss*HD];
__device__ float g_k[Bb*Hh*Ss*HD];
__device__ float g_v[Bb*Hh*Ss*HD];
__device__ float g_wv[Bb*Ss*Dd];
__device__ float g_invf[32];

// ---------------------------------------------------------------------------
__device__ __forceinline__ float tf32r(float x) {
    unsigned int u;
    asm("cvt.rna.tf32.f32 %0, %1;" : "=r"(u) : "f"(x));
    return __uint_as_float(u);
}
__device__ __forceinline__ unsigned int tf32u(float x) {
    unsigned int u;
    asm("cvt.rna.tf32.f32 %0, %1;" : "=r"(u) : "f"(x));
    return u;
}

__device__ __forceinline__ void mma_tf32(float* d, const unsigned int* a, const unsigned int* b) {
    asm volatile(
        "mma.sync.aligned.m16n8k8.row.col.f32.tf32.tf32.f32 "
        "{%0,%1,%2,%3}, {%4,%5,%6,%7}, {%8,%9}, {%0,%1,%2,%3};"
        : "+f"(d[0]), "+f"(d[1]), "+f"(d[2]), "+f"(d[3])
        : "r"(a[0]), "r"(a[1]), "r"(a[2]), "r"(a[3]), "r"(b[0]), "r"(b[1]));
}

__device__ __forceinline__ void cp16(unsigned int dst, const void* src) {
    asm volatile("cp.async.ca.shared.global [%0], [%1], 16;\n" :: "r"(dst), "l"(src));
}
__device__ __forceinline__ void cp_commit() {
    asm volatile("cp.async.commit_group;\n");
}
template<int N>
__device__ __forceinline__ void cp_wait() {
    asm volatile("cp.async.wait_group %0;\n" :: "n"(N));
}

// ---------------------------------------------------------------------------
__global__ void init_invf_kernel() {
    int j = threadIdx.x;
    if (j < 32)
        g_invf[j] = (float)exp(-9.210340371976184 * ((double)j / 32.0));
}

__global__ void init_cache_kernel(const float4* __restrict__ kc,
                                  const float4* __restrict__ vc) {
    int i = blockIdx.x * blockDim.x + threadIdx.x;
    ((float4*)g_k)[i] = kc[i];
    ((float4*)g_v)[i] = vc[i];
}

// ---------------------------------------------------------------------------
// tf32 tensor-core GEMM, 3-stage cp.async: C[m][n] = sum_k X[m][k]*W[n][k](+b)
// BM=128, BN=64, BK=16; 256 thr = 8 warps (4Mx2N), warp tile 32x32.
// Smem per stage: As[128][20] + Bs[64][20] (fp32 raw; tf32 cvt at frag load).
// 3 stages = 46080 B, unioned with epilogue Cs[128][68].
// ---------------------------------------------------------------------------
#define GSTG 3840           // floats per stage
#define ASOFF(st,m,k) ((st)*GSTG + (m)*20 + (k))
#define BSOFF(st,n,k) ((st)*GSTG + 2560 + (n)*20 + (k))

template<int MODE>
__global__ void __launch_bounds__(256) gemm_kernel(
    const float* __restrict__ X, const float* __restrict__ W,
    const float* __restrict__ bias, float* __restrict__ out,
    const int* __restrict__ rope_pos, const int* __restrict__ scat_pos)
{
    const int K = Dd;
    __shared__ __align__(16) float sm[3*GSTG];   // 46080 B
    float (*Cs)[68] = (float(*)[68])sm;          // epilogue (after sync)
    unsigned int smb = (unsigned int)__cvta_generic_to_shared(sm);

    const int tid  = threadIdx.x;
    const int warp = tid >> 5, lane = tid & 31;
    const int wy = warp & 3, wx = warp >> 2;
    const int lr = lane >> 2, lc = lane & 3;
    const int m0 = blockIdx.y * 128, n0 = blockIdx.x * 64;

    const float* Xb = X + (size_t)m0 * K;
    const float* Wb = W + (size_t)n0 * K;

    // staging assignment: 768 16B-chunks/stage, 3 per thread
    const int ar0 = tid >> 1;                 // As rows: tid/2 (two chunks each)
    const int ak0 = (tid & 1) * 2;            // chunk cols 0/1 or 2/3
    const int br  = tid >> 2, bk = tid & 3;   // Bs: one chunk

    auto issue = [&](int i) {
        int kt = i * 16, st = i % 3;
        cp16(smb + 4*ASOFF(st, ar0, ak0*4),     Xb + (size_t)ar0 * K + kt + ak0*4);
        cp16(smb + 4*ASOFF(st, ar0, (ak0+1)*4), Xb + (size_t)ar0 * K + kt + (ak0+1)*4);
        cp16(smb + 4*BSOFF(st, br, bk*4),       Wb + (size_t)br  * K + kt + bk*4);
    };

    float acc[2][4][4] = {};

    issue(0); cp_commit();
    issue(1); cp_commit();

    const int NT = K / 16;   // 64
    for (int i = 0; i < NT; i++) {
        cp_wait<1>();
        __syncthreads();
        if (i + 2 < NT) issue(i + 2);
        cp_commit();

        const int cb = i % 3;
#pragma unroll
        for (int kf = 0; kf < 16; kf += 8) {
            unsigned int a[2][4], b[4][2];
#pragma unroll
            for (int mf = 0; mf < 2; mf++) {
                int m = wy*32 + mf*16 + lr;
                a[mf][0] = tf32u(sm[ASOFF(cb, m,   kf+lc)]);
                a[mf][1] = tf32u(sm[ASOFF(cb, m+8, kf+lc)]);
                a[mf][2] = tf32u(sm[ASOFF(cb, m,   kf+4+lc)]);
                a[mf][3] = tf32u(sm[ASOFF(cb, m+8, kf+4+lc)]);
            }
#pragma unroll
            for (int nf = 0; nf < 4; nf++) {
                int n = wx*32 + nf*8 + lr;
                b[nf][0] = tf32u(sm[BSOFF(cb, n, kf+lc)]);
                b[nf][1] = tf32u(sm[BSOFF(cb, n, kf+4+lc)]);
            }
#pragma unroll
            for (int mf = 0; mf < 2; mf++)
#pragma unroll
                for (int nf = 0; nf < 4; nf++)
                    mma_tf32(acc[mf][nf], a[mf], b[nf]);
        }
    }

    if (MODE == 0) {
#pragma unroll
        for (int mf = 0; mf < 2; mf++)
#pragma unroll
            for (int nf = 0; nf < 4; nf++) {
                int mA = m0 + wy*32 + mf*16 + lr;
                int nA = n0 + wx*32 + nf*8 + 2*lc;
                float b0 = bias ? bias[nA]   : 0.f;
                float b1 = bias ? bias[nA+1] : 0.f;
                out[(size_t)mA     * Dd + nA    ] = acc[mf][nf][0] + b0;
                out[(size_t)mA     * Dd + nA + 1] = acc[mf][nf][1] + b1;
                out[(size_t)(mA+8) * Dd + nA    ] = acc[mf][nf][2] + b0;
                out[(size_t)(mA+8) * Dd + nA + 1] = acc[mf][nf][3] + b1;
            }
        return;
    }

    // MODE 1: stage into Cs (overlaps stage buffers -> sync first)
    __syncthreads();
#pragma unroll
    for (int mf = 0; mf < 2; mf++)
#pragma unroll
        for (int nf = 0; nf < 4; nf++) {
            int r = wy*32 + mf*16 + lr;
            int c = wx*32 + nf*8 + 2*lc;
            float b0 = bias ? bias[n0 + c]     : 0.f;
            float b1 = bias ? bias[n0 + c + 1] : 0.f;
            Cs[r  ][c  ] = acc[mf][nf][0] + b0;
            Cs[r  ][c+1] = acc[mf][nf][1] + b1;
            Cs[r+8][c  ] = acc[mf][nf][2] + b0;
            Cs[r+8][c+1] = acc[mf][nf][3] + b1;
        }
    __syncthreads();

    const int tx = tid & 15, ty = tid >> 4;
    const int h = n0 >> 6;
    float invf4[4];
#pragma unroll
    for (int j = 0; j < 4; j++) invf4[j] = g_invf[(tx*4 + j) & 31];

#pragma unroll
    for (int i = 0; i < 8; i++) {
        int row = ty*8 + i;
        int m = m0 + row;
        int b = m >> 11;
        int s = m & 2047;
        int dst = scat_pos ? scat_pos[s] : s;
        float* orow = out + (((size_t)(b*Hh + h)) * Ss + dst) * HD;
        if (rope_pos) {
            float p = (float)rope_pos[s];
#pragma unroll
            for (int j = 0; j < 4; j++) {
                int d = tx*4 + j;
                float x   = Cs[row][d];
                float rot = (d < 32) ? -Cs[row][d+32] : Cs[row][d-32];
                float ang = p * invf4[j];
                orow[d] = x * cosf(ang) + rot * sinf(ang);
            }
        } else {
#pragma unroll
            for (int j = 0; j < 4; j++)
                orow[tx*4+j] = Cs[row][tx*4+j];
        }
    }
}

// ---------------------------------------------------------------------------
// tf32 tensor-core causal flash attention.
// Grid (Ss/128, B*H), 256 thr = 8 warps. Br=128, Bc=64, warp tile 16x64.
// K and V both staged coalesced row-major; pads chosen conflict-free.
// ---------------------------------------------------------------------------
__global__ void __launch_bounds__(256, 1) attn_kernel(float* __restrict__ wv)
{
    extern __shared__ float smf[];
    float (*Qs)[68] = (float(*)[68])smf;                 // also Ps
    float (*Ks)[68] = (float(*)[68])(smf + 8704);        // [kv][d] pad 68
    float (*Vs)[72] = (float(*)[72])(smf + 8704 + 4352); // [kv][d] pad 72

    const int tid  = threadIdx.x;
    const int warp = tid >> 5, lane = tid & 31;
    const int lr = lane >> 2, lc = lane & 3;
    const int bh = blockIdx.y;
    const int qt = (int)gridDim.x - 1 - (int)blockIdx.x; // heavy blocks first
    const int qb = qt * 128;

    const float* Qg = g_q + ((size_t)bh * Ss + qb) * HD;
    const float* Kg = g_k + (size_t)bh * Ss * HD;
    const float* Vg = g_v + (size_t)bh * Ss * HD;

    // stage Q (x 1/8, tf32)
#pragma unroll
    for (int it = 0; it < 8; it++) {
        int idx = tid + it*256;
        int r = idx >> 4, c4 = idx & 15;
        float4 v = *(const float4*)(Qg + (size_t)r*HD + c4*4);
        float4 o4;
        o4.x = tf32r(v.x * 0.125f); o4.y = tf32r(v.y * 0.125f);
        o4.z = tf32r(v.z * 0.125f); o4.w = tf32r(v.w * 0.125f);
        *(float4*)&Qs[r][c4*4] = o4;
    }
    __syncthreads();

    // Q fragments -> registers
    const int mrow = warp*16 + lr;
    unsigned int qa[8][4];
#pragma unroll
    for (int ks = 0; ks < 8; ks++) {
        int d0 = ks*8;
        qa[ks][0] = __float_as_uint(Qs[mrow  ][d0+lc]);
        qa[ks][1] = __float_as_uint(Qs[mrow+8][d0+lc]);
        qa[ks][2] = __float_as_uint(Qs[mrow  ][d0+4+lc]);
        qa[ks][3] = __float_as_uint(Qs[mrow+8][d0+4+lc]);
    }

    float o[8][4] = {};
    float m_i[2] = {-3.0e38f, -3.0e38f};
    float l_i[2] = {0.f, 0.f};

    const int jmax = 2*qt + 1;
    for (int jt = 0; jt <= jmax; jt++) {
        __syncthreads();
        // stage K coalesced [kv][d]
#pragma unroll
        for (int it = 0; it < 4; it++) {
            int idx = tid + it*256;
            int r = idx >> 4, c4 = idx & 15;
            float4 v = *(const float4*)(Kg + (size_t)(jt*64 + r)*HD + c4*4);
            float4 o4;
            o4.x = tf32r(v.x); o4.y = tf32r(v.y);
            o4.z = tf32r(v.z); o4.w = tf32r(v.w);
            *(float4*)&Ks[r][c4*4] = o4;
        }
        // stage V coalesced [kv][d]
#pragma unroll
        for (int it = 0; it < 4; it++) {
            int idx = tid + it*256;
            int r = idx >> 4, c4 = idx & 15;
            float4 v = *(const float4*)(Vg + (size_t)(jt*64 + r)*HD + c4*4);
            float4 o4;
            o4.x = tf32r(v.x); o4.y = tf32r(v.y);
            o4.z = tf32r(v.z); o4.w = tf32r(v.w);
            *(float4*)&Vs[r][c4*4] = o4;
        }
        __syncthreads();

        // S = (Q/8) K^T   (16x64 per warp);  B[n=kv][k=d] col-major = Ks[kv][d]
        float sacc[8][4] = {};
#pragma unroll
        for (int ks = 0; ks < 8; ks++) {
            int d0 = ks*8;
#pragma unroll
            for (int nf = 0; nf < 8; nf++) {
                unsigned int b[2];
                b[0] = __float_as_uint(Ks[nf*8+lr][d0+lc]);
                b[1] = __float_as_uint(Ks[nf*8+lr][d0+4+lc]);
                mma_tf32(sacc[nf], qa[ks], b);
            }
        }

        // causal mask (only the 2 diagonal tiles)
        if (jt >= 2*qt) {
            int row0 = qb + warp*16 + lr;
#pragma unroll
            for (int nf = 0; nf < 8; nf++) {
                int col = jt*64 + nf*8 + 2*lc;
                if (col   > row0)     sacc[nf][0] = -1.0e30f;
                if (col+1 > row0)     sacc[nf][1] = -1.0e30f;
                if (col   > row0+8)   sacc[nf][2] = -1.0e30f;
                if (col+1 > row0+8)   sacc[nf][3] = -1.0e30f;
            }
        }

        // online softmax
        float rmax0 = -3.0e38f, rmax1 = -3.0e38f;
#pragma unroll
        for (int nf = 0; nf < 8; nf++) {
            rmax0 = fmaxf(rmax0, fmaxf(sacc[nf][0], sacc[nf][1]));
            rmax1 = fmaxf(rmax1, fmaxf(sacc[nf][2], sacc[nf][3]));
        }
        rmax0 = fmaxf(rmax0, __shfl_xor_sync(0xffffffffu, rmax0, 1));
        rmax0 = fmaxf(rmax0, __shfl_xor_sync(0xffffffffu, rmax0, 2));
        rmax1 = fmaxf(rmax1, __shfl_xor_sync(0xffffffffu, rmax1, 1));
        rmax1 = fmaxf(rmax1, __shfl_xor_sync(0xffffffffu, rmax1, 2));

        float mn0 = fmaxf(m_i[0], rmax0);
        float mn1 = fmaxf(m_i[1], rmax1);
        float al0 = __expf(m_i[0] - mn0);
        float al1 = __expf(m_i[1] - mn1);
        m_i[0] = mn0; m_i[1] = mn1;

        float ls0 = 0.f, ls1 = 0.f;
#pragma unroll
        for (int nf = 0; nf < 8; nf++) {
            sacc[nf][0] = __expf(sacc[nf][0] - mn0);
            sacc[nf][1] = __expf(sacc[nf][1] - mn0);
            sacc[nf][2] = __expf(sacc[nf][2] - mn1);
            sacc[nf][3] = __expf(sacc[nf][3] - mn1);
            ls0 += sacc[nf][0] + sacc[nf][1];
            ls1 += sacc[nf][2] + sacc[nf][3];
        }
        ls0 += __shfl_xor_sync(0xffffffffu, ls0, 1);
        ls0 += __shfl_xor_sync(0xffffffffu, ls0, 2);
        ls1 += __shfl_xor_sync(0xffffffffu, ls1, 1);
        ls1 += __shfl_xor_sync(0xffffffffu, ls1, 2);
        l_i[0] = l_i[0]*al0 + ls0;
        l_i[1] = l_i[1]*al1 + ls1;

#pragma unroll
        for (int nf = 0; nf < 8; nf++) {
            o[nf][0] *= al0; o[nf][1] *= al0;
            o[nf][2] *= al1; o[nf][3] *= al1;
        }

        // store P (tf32) into Ps (=Qs) rows owned by this warp only
#pragma unroll
        for (int nf = 0; nf < 8; nf++) {
            float2 p0, p1;
            p0.x = tf32r(sacc[nf][0]); p0.y = tf32r(sacc[nf][1]);
            p1.x = tf32r(sacc[nf][2]); p1.y = tf32r(sacc[nf][3]);
            *(float2*)&Qs[mrow  ][nf*8 + 2*lc] = p0;
            *(float2*)&Qs[mrow+8][nf*8 + 2*lc] = p1;
        }
        __syncwarp();

        // O += P V
#pragma unroll
        for (int ks = 0; ks < 8; ks++) {
            int k0 = ks*8;
            unsigned int ap[4];
            ap[0] = __float_as_uint(Qs[mrow  ][k0+lc]);
            ap[1] = __float_as_uint(Qs[mrow+8][k0+lc]);
            ap[2] = __float_as_uint(Qs[mrow  ][k0+4+lc]);
            ap[3] = __float_as_uint(Qs[mrow+8][k0+4+lc]);
#pragma unroll
            for (int nf = 0; nf < 8; nf++) {
                unsigned int b[2];
                b[0] = __float_as_uint(Vs[k0+lc  ][nf*8+lr]);
                b[1] = __float_as_uint(Vs[k0+4+lc][nf*8+lr]);
                mma_tf32(o[nf], ap, b);
            }
        }
    }

    const int b = bh >> 4, h = bh & 15;
    const float inv0 = 1.f / l_i[0];
    const float inv1 = 1.f / l_i[1];
    const int s0 = qb + warp*16 + lr;
    float* row0 = wv + ((size_t)(b*Ss + s0)) * Dd + h*HD;
    float* row1 = row0 + (size_t)8 * Dd;
#pragma unroll
    for (int nf = 0; nf < 8; nf++) {
        float2 w0, w1;
        w0.x = o[nf][0]*inv0; w0.y = o[nf][1]*inv0;
        w1.x = o[nf][2]*inv1; w1.y = o[nf][3]*inv1;
        *(float2*)&row0[nf*8 + 2*lc] = w0;
        *(float2*)&row1[nf*8 + 2*lc] = w1;
    }
}

// ---------------------------------------------------------------------------
extern "C" void kernel_launch(void* const* d_in, const int* in_sizes, int n_in,
                              void* d_out, int out_size)
{
    const float* qx      = (const float*)d_in[0];
    const float* kvx     = (const float*)d_in[1];
    const float* k_cache = (const float*)d_in[2];
    const float* v_cache = (const float*)d_in[3];
    const float* Wq      = (const float*)d_in[4];
    const float* bq      = (const float*)d_in[5];
    const float* Wk      = (const float*)d_in[6];
    const float* Wv      = (const float*)d_in[7];
    const float* bv      = (const float*)d_in[8];
    const float* Wo      = (const float*)d_in[9];
    const float* bo      = (const float*)d_in[10];
    const int*   qpos    = (const int*)d_in[11];
    const int*   kpos    = (const int*)d_in[12];
    float* out = (float*)d_out;

    const int attn_smem = (8704 + 4352 + 4608) * 4;   // 70656 B
    cudaFuncSetAttribute(attn_kernel, cudaFuncAttributeMaxDynamicSharedMemorySize, attn_smem);

    float *pq, *pk, *pv, *pwv;
    cudaGetSymbolAddress((void**)&pq,  g_q);
    cudaGetSymbolAddress((void**)&pk,  g_k);
    cudaGetSymbolAddress((void**)&pv,  g_v);
    cudaGetSymbolAddress((void**)&pwv, g_wv);

    init_invf_kernel<<<1, 32>>>();
    init_cache_kernel<<<(Bb*Hh*Ss*HD/4 + 255)/256, 256>>>((const float4*)k_cache,
                                                          (const float4*)v_cache);

    dim3 gg(Dd/64, Mm/128);   // (16, 32)
    gemm_kernel<1><<<gg, 256>>>(qx,  Wq, bq,      pq,  qpos, nullptr);
    gemm_kernel<1><<<gg, 256>>>(kvx, Wk, nullptr, pk,  kpos, kpos);
    gemm_kernel<1><<<gg, 256>>>(kvx, Wv, bv,      pv,  nullptr, kpos);

    attn_kernel<<<dim3(Ss/128, Bb*Hh), 256, attn_smem>>>(pwv);

    gemm_kernel<0><<<gg, 256>>>(pwv, Wo, bo, out, nullptr, nullptr);
}

// round 12
// speedup vs baseline: 1.0009x; 1.0009x over previous
#include <cuda_runtime.h>
#include <cstdint>
#include <math.h>

#define Bb 2
#define Ss 2048
#define Dd 1024
#define Hh 16
#define HD 64
#define Mm (Bb*Ss)

// Scratch (allocation-free: __device__ globals)
__device__ float g_q[Bb*Hh*Ss*HD];
__device__ float g_k[Bb*Hh*Ss*HD];
__device__ float g_v[Bb*Hh*Ss*HD];
__device__ float g_wv[Bb*Ss*Dd];
__device__ float g_invf[32];

// ---------------------------------------------------------------------------
__device__ __forceinline__ float tf32r(float x) {
    unsigned int u;
    asm("cvt.rna.tf32.f32 %0, %1;" : "=r"(u) : "f"(x));
    return __uint_as_float(u);
}
__device__ __forceinline__ unsigned int tf32u(float x) {
    unsigned int u;
    asm("cvt.rna.tf32.f32 %0, %1;" : "=r"(u) : "f"(x));
    return u;
}

__device__ __forceinline__ void mma_tf32(float* d, const unsigned int* a, const unsigned int* b) {
    asm volatile(
        "mma.sync.aligned.m16n8k8.row.col.f32.tf32.tf32.f32 "
        "{%0,%1,%2,%3}, {%4,%5,%6,%7}, {%8,%9}, {%0,%1,%2,%3};"
        : "+f"(d[0]), "+f"(d[1]), "+f"(d[2]), "+f"(d[3])
        : "r"(a[0]), "r"(a[1]), "r"(a[2]), "r"(a[3]), "r"(b[0]), "r"(b[1]));
}

__device__ __forceinline__ void cp16(unsigned int dst, const void* src) {
    asm volatile("cp.async.ca.shared.global [%0], [%1], 16;\n" :: "r"(dst), "l"(src));
}
__device__ __forceinline__ void cp_commit() {
    asm volatile("cp.async.commit_group;\n");
}
template<int N>
__device__ __forceinline__ void cp_wait() {
    asm volatile("cp.async.wait_group %0;\n" :: "n"(N));
}

// ---------------------------------------------------------------------------
__global__ void init_invf_kernel() {
    int j = threadIdx.x;
    if (j < 32)
        g_invf[j] = (float)exp(-9.210340371976184 * ((double)j / 32.0));
}

__global__ void init_cache_kernel(const float4* __restrict__ kc,
                                  const float4* __restrict__ vc) {
    int i = blockIdx.x * blockDim.x + threadIdx.x;
    ((float4*)g_k)[i] = kc[i];
    ((float4*)g_v)[i] = vc[i];
}

// ---------------------------------------------------------------------------
// tf32 tensor-core GEMM, 3-stage cp.async: C[m][n] = sum_k X[m][k]*W[n][k](+b)
// BM=128, BN=64, BK=16; 256 thr = 8 warps (4Mx2N), warp tile 32x32.
// Smem per stage: As[128][20] + Bs[64][20] (fp32 raw; tf32 cvt at frag load).
// 3 stages = 46080 B, unioned with epilogue Cs[128][68].
// ---------------------------------------------------------------------------
#define GSTG 3840           // floats per stage
#define ASOFF(st,m,k) ((st)*GSTG + (m)*20 + (k))
#define BSOFF(st,n,k) ((st)*GSTG + 2560 + (n)*20 + (k))

template<int MODE>
__global__ void __launch_bounds__(256) gemm_kernel(
    const float* __restrict__ X, const float* __restrict__ W,
    const float* __restrict__ bias, float* __restrict__ out,
    const int* __restrict__ rope_pos, const int* __restrict__ scat_pos)
{
    const int K = Dd;
    __shared__ __align__(16) float sm[3*GSTG];   // 46080 B
    float (*Cs)[68] = (float(*)[68])sm;          // epilogue (after sync)
    unsigned int smb = (unsigned int)__cvta_generic_to_shared(sm);

    const int tid  = threadIdx.x;
    const int warp = tid >> 5, lane = tid & 31;
    const int wy = warp & 3, wx = warp >> 2;
    const int lr = lane >> 2, lc = lane & 3;
    const int m0 = blockIdx.y * 128, n0 = blockIdx.x * 64;

    const float* Xb = X + (size_t)m0 * K;
    const float* Wb = W + (size_t)n0 * K;

    // staging assignment: 768 16B-chunks/stage, 3 per thread
    const int ar0 = tid >> 1;                 // As rows: tid/2 (two chunks each)
    const int ak0 = (tid & 1) * 2;            // chunk cols 0/1 or 2/3
    const int br  = tid >> 2, bk = tid & 3;   // Bs: one chunk

    auto issue = [&](int i) {
        int kt = i * 16, st = i % 3;
        cp16(smb + 4*ASOFF(st, ar0, ak0*4),     Xb + (size_t)ar0 * K + kt + ak0*4);
        cp16(smb + 4*ASOFF(st, ar0, (ak0+1)*4), Xb + (size_t)ar0 * K + kt + (ak0+1)*4);
        cp16(smb + 4*BSOFF(st, br, bk*4),       Wb + (size_t)br  * K + kt + bk*4);
    };

    float acc[2][4][4] = {};

    issue(0); cp_commit();
    issue(1); cp_commit();

    const int NT = K / 16;   // 64
    for (int i = 0; i < NT; i++) {
        cp_wait<1>();
        __syncthreads();
        if (i + 2 < NT) issue(i + 2);
        cp_commit();

        const int cb = i % 3;
#pragma unroll
        for (int kf = 0; kf < 16; kf += 8) {
            unsigned int a[2][4], b[4][2];
#pragma unroll
            for (int mf = 0; mf < 2; mf++) {
                int m = wy*32 + mf*16 + lr;
                a[mf][0] = tf32u(sm[ASOFF(cb, m,   kf+lc)]);
                a[mf][1] = tf32u(sm[ASOFF(cb, m+8, kf+lc)]);
                a[mf][2] = tf32u(sm[ASOFF(cb, m,   kf+4+lc)]);
                a[mf][3] = tf32u(sm[ASOFF(cb, m+8, kf+4+lc)]);
            }
#pragma unroll
            for (int nf = 0; nf < 4; nf++) {
                int n = wx*32 + nf*8 + lr;
                b[nf][0] = tf32u(sm[BSOFF(cb, n, kf+lc)]);
                b[nf][1] = tf32u(sm[BSOFF(cb, n, kf+4+lc)]);
            }
#pragma unroll
            for (int mf = 0; mf < 2; mf++)
#pragma unroll
                for (int nf = 0; nf < 4; nf++)
                    mma_tf32(acc[mf][nf], a[mf], b[nf]);
        }
    }

    if (MODE == 0) {
#pragma unroll
        for (int mf = 0; mf < 2; mf++)
#pragma unroll
            for (int nf = 0; nf < 4; nf++) {
                int mA = m0 + wy*32 + mf*16 + lr;
                int nA = n0 + wx*32 + nf*8 + 2*lc;
                float b0 = bias ? bias[nA]   : 0.f;
                float b1 = bias ? bias[nA+1] : 0.f;
                out[(size_t)mA     * Dd + nA    ] = acc[mf][nf][0] + b0;
                out[(size_t)mA     * Dd + nA + 1] = acc[mf][nf][1] + b1;
                out[(size_t)(mA+8) * Dd + nA    ] = acc[mf][nf][2] + b0;
                out[(size_t)(mA+8) * Dd + nA + 1] = acc[mf][nf][3] + b1;
            }
        return;
    }

    // MODE 1: stage into Cs (overlaps stage buffers -> sync first)
    __syncthreads();
#pragma unroll
    for (int mf = 0; mf < 2; mf++)
#pragma unroll
        for (int nf = 0; nf < 4; nf++) {
            int r = wy*32 + mf*16 + lr;
            int c = wx*32 + nf*8 + 2*lc;
            float b0 = bias ? bias[n0 + c]     : 0.f;
            float b1 = bias ? bias[n0 + c + 1] : 0.f;
            Cs[r  ][c  ] = acc[mf][nf][0] + b0;
            Cs[r  ][c+1] = acc[mf][nf][1] + b1;
            Cs[r+8][c  ] = acc[mf][nf][2] + b0;
            Cs[r+8][c+1] = acc[mf][nf][3] + b1;
        }
    __syncthreads();

    const int tx = tid & 15, ty = tid >> 4;
    const int h = n0 >> 6;
    float invf4[4];
#pragma unroll
    for (int j = 0; j < 4; j++) invf4[j] = g_invf[(tx*4 + j) & 31];

#pragma unroll
    for (int i = 0; i < 8; i++) {
        int row = ty*8 + i;
        int m = m0 + row;
        int b = m >> 11;
        int s = m & 2047;
        int dst = scat_pos ? scat_pos[s] : s;
        float* orow = out + (((size_t)(b*Hh + h)) * Ss + dst) * HD;
        if (rope_pos) {
            float p = (float)rope_pos[s];
#pragma unroll
            for (int j = 0; j < 4; j++) {
                int d = tx*4 + j;
                float x   = Cs[row][d];
                float rot = (d < 32) ? -Cs[row][d+32] : Cs[row][d-32];
                float ang = p * invf4[j];
                orow[d] = x * cosf(ang) + rot * sinf(ang);
            }
        } else {
#pragma unroll
            for (int j = 0; j < 4; j++)
                orow[tx*4+j] = Cs[row][tx*4+j];
        }
    }
}

// ---------------------------------------------------------------------------
// tf32 tensor-core causal flash attention.
// Grid (Ss/128, B*H), 256 thr = 8 warps. Br=128, Bc=64, warp tile 16x64.
// K and V both staged coalesced row-major; pads chosen conflict-free.
// ---------------------------------------------------------------------------
__global__ void __launch_bounds__(256, 1) attn_kernel(float* __restrict__ wv)
{
    extern __shared__ float smf[];
    float (*Qs)[68] = (float(*)[68])smf;                 // also Ps
    float (*Ks)[68] = (float(*)[68])(smf + 8704);        // [kv][d] pad 68
    float (*Vs)[72] = (float(*)[72])(smf + 8704 + 4352); // [kv][d] pad 72

    const int tid  = threadIdx.x;
    const int warp = tid >> 5, lane = tid & 31;
    const int lr = lane >> 2, lc = lane & 3;
    const int bh = blockIdx.y;
    const int qt = (int)gridDim.x - 1 - (int)blockIdx.x; // heavy blocks first
    const int qb = qt * 128;

    const float* Qg = g_q + ((size_t)bh * Ss + qb) * HD;
    const float* Kg = g_k + (size_t)bh * Ss * HD;
    const float* Vg = g_v + (size_t)bh * Ss * HD;

    // stage Q (x 1/8, tf32)
#pragma unroll
    for (int it = 0; it < 8; it++) {
        int idx = tid + it*256;
        int r = idx >> 4, c4 = idx & 15;
        float4 v = *(const float4*)(Qg + (size_t)r*HD + c4*4);
        float4 o4;
        o4.x = tf32r(v.x * 0.125f); o4.y = tf32r(v.y * 0.125f);
        o4.z = tf32r(v.z * 0.125f); o4.w = tf32r(v.w * 0.125f);
        *(float4*)&Qs[r][c4*4] = o4;
    }
    __syncthreads();

    // Q fragments -> registers
    const int mrow = warp*16 + lr;
    unsigned int qa[8][4];
#pragma unroll
    for (int ks = 0; ks < 8; ks++) {
        int d0 = ks*8;
        qa[ks][0] = __float_as_uint(Qs[mrow  ][d0+lc]);
        qa[ks][1] = __float_as_uint(Qs[mrow+8][d0+lc]);
        qa[ks][2] = __float_as_uint(Qs[mrow  ][d0+4+lc]);
        qa[ks][3] = __float_as_uint(Qs[mrow+8][d0+4+lc]);
    }

    float o[8][4] = {};
    float m_i[2] = {-3.0e38f, -3.0e38f};
    float l_i[2] = {0.f, 0.f};

    const int jmax = 2*qt + 1;
    for (int jt = 0; jt <= jmax; jt++) {
        __syncthreads();
        // stage K coalesced [kv][d]
#pragma unroll
        for (int it = 0; it < 4; it++) {
            int idx = tid + it*256;
            int r = idx >> 4, c4 = idx & 15;
            float4 v = *(const float4*)(Kg + (size_t)(jt*64 + r)*HD + c4*4);
            float4 o4;
            o4.x = tf32r(v.x); o4.y = tf32r(v.y);
            o4.z = tf32r(v.z); o4.w = tf32r(v.w);
            *(float4*)&Ks[r][c4*4] = o4;
        }
        // stage V coalesced [kv][d]
#pragma unroll
        for (int it = 0; it < 4; it++) {
            int idx = tid + it*256;
            int r = idx >> 4, c4 = idx & 15;
            float4 v = *(const float4*)(Vg + (size_t)(jt*64 + r)*HD + c4*4);
            float4 o4;
            o4.x = tf32r(v.x); o4.y = tf32r(v.y);
            o4.z = tf32r(v.z); o4.w = tf32r(v.w);
            *(float4*)&Vs[r][c4*4] = o4;
        }
        __syncthreads();

        // S = (Q/8) K^T   (16x64 per warp);  B[n=kv][k=d] col-major = Ks[kv][d]
        float sacc[8][4] = {};
#pragma unroll
        for (int ks = 0; ks < 8; ks++) {
            int d0 = ks*8;
#pragma unroll
            for (int nf = 0; nf < 8; nf++) {
                unsigned int b[2];
                b[0] = __float_as_uint(Ks[nf*8+lr][d0+lc]);
                b[1] = __float_as_uint(Ks[nf*8+lr][d0+4+lc]);
                mma_tf32(sacc[nf], qa[ks], b);
            }
        }

        // causal mask (only the 2 diagonal tiles)
        if (jt >= 2*qt) {
            int row0 = qb + warp*16 + lr;
#pragma unroll
            for (int nf = 0; nf < 8; nf++) {
                int col = jt*64 + nf*8 + 2*lc;
                if (col   > row0)     sacc[nf][0] = -1.0e30f;
                if (col+1 > row0)     sacc[nf][1] = -1.0e30f;
                if (col   > row0+8)   sacc[nf][2] = -1.0e30f;
                if (col+1 > row0+8)   sacc[nf][3] = -1.0e30f;
            }
        }

        // online softmax
        float rmax0 = -3.0e38f, rmax1 = -3.0e38f;
#pragma unroll
        for (int nf = 0; nf < 8; nf++) {
            rmax0 = fmaxf(rmax0, fmaxf(sacc[nf][0], sacc[nf][1]));
            rmax1 = fmaxf(rmax1, fmaxf(sacc[nf][2], sacc[nf][3]));
        }
        rmax0 = fmaxf(rmax0, __shfl_xor_sync(0xffffffffu, rmax0, 1));
        rmax0 = fmaxf(rmax0, __shfl_xor_sync(0xffffffffu, rmax0, 2));
        rmax1 = fmaxf(rmax1, __shfl_xor_sync(0xffffffffu, rmax1, 1));
        rmax1 = fmaxf(rmax1, __shfl_xor_sync(0xffffffffu, rmax1, 2));

        float mn0 = fmaxf(m_i[0], rmax0);
        float mn1 = fmaxf(m_i[1], rmax1);
        float al0 = __expf(m_i[0] - mn0);
        float al1 = __expf(m_i[1] - mn1);
        m_i[0] = mn0; m_i[1] = mn1;

        float ls0 = 0.f, ls1 = 0.f;
#pragma unroll
        for (int nf = 0; nf < 8; nf++) {
            sacc[nf][0] = __expf(sacc[nf][0] - mn0);
            sacc[nf][1] = __expf(sacc[nf][1] - mn0);
            sacc[nf][2] = __expf(sacc[nf][2] - mn1);
            sacc[nf][3] = __expf(sacc[nf][3] - mn1);
            ls0 += sacc[nf][0] + sacc[nf][1];
            ls1 += sacc[nf][2] + sacc[nf][3];
        }
        ls0 += __shfl_xor_sync(0xffffffffu, ls0, 1);
        ls0 += __shfl_xor_sync(0xffffffffu, ls0, 2);
        ls1 += __shfl_xor_sync(0xffffffffu, ls1, 1);
        ls1 += __shfl_xor_sync(0xffffffffu, ls1, 2);
        l_i[0] = l_i[0]*al0 + ls0;
        l_i[1] = l_i[1]*al1 + ls1;

#pragma unroll
        for (int nf = 0; nf < 8; nf++) {
            o[nf][0] *= al0; o[nf][1] *= al0;
            o[nf][2] *= al1; o[nf][3] *= al1;
        }

        // store P (tf32) into Ps (=Qs) rows owned by this warp only
#pragma unroll
        for (int nf = 0; nf < 8; nf++) {
            float2 p0, p1;
            p0.x = tf32r(sacc[nf][0]); p0.y = tf32r(sacc[nf][1]);
            p1.x = tf32r(sacc[nf][2]); p1.y = tf32r(sacc[nf][3]);
            *(float2*)&Qs[mrow  ][nf*8 + 2*lc] = p0;
            *(float2*)&Qs[mrow+8][nf*8 + 2*lc] = p1;
        }
        __syncwarp();

        // O += P V
#pragma unroll
        for (int ks = 0; ks < 8; ks++) {
            int k0 = ks*8;
            unsigned int ap[4];
            ap[0] = __float_as_uint(Qs[mrow  ][k0+lc]);
            ap[1] = __float_as_uint(Qs[mrow+8][k0+lc]);
            ap[2] = __float_as_uint(Qs[mrow  ][k0+4+lc]);
            ap[3] = __float_as_uint(Qs[mrow+8][k0+4+lc]);
#pragma unroll
            for (int nf = 0; nf < 8; nf++) {
                unsigned int b[2];
                b[0] = __float_as_uint(Vs[k0+lc  ][nf*8+lr]);
                b[1] = __float_as_uint(Vs[k0+4+lc][nf*8+lr]);
                mma_tf32(o[nf], ap, b);
            }
        }
    }

    const int b = bh >> 4, h = bh & 15;
    const float inv0 = 1.f / l_i[0];
    const float inv1 = 1.f / l_i[1];
    const int s0 = qb + warp*16 + lr;
    float* row0 = wv + ((size_t)(b*Ss + s0)) * Dd + h*HD;
    float* row1 = row0 + (size_t)8 * Dd;
#pragma unroll
    for (int nf = 0; nf < 8; nf++) {
        float2 w0, w1;
        w0.x = o[nf][0]*inv0; w0.y = o[nf][1]*inv0;
        w1.x = o[nf][2]*inv1; w1.y = o[nf][3]*inv1;
        *(float2*)&row0[nf*8 + 2*lc] = w0;
        *(float2*)&row1[nf*8 + 2*lc] = w1;
    }
}

// ---------------------------------------------------------------------------
extern "C" void kernel_launch(void* const* d_in, const int* in_sizes, int n_in,
                              void* d_out, int out_size)
{
    const float* qx      = (const float*)d_in[0];
    const float* kvx     = (const float*)d_in[1];
    const float* k_cache = (const float*)d_in[2];
    const float* v_cache = (const float*)d_in[3];
    const float* Wq      = (const float*)d_in[4];
    const float* bq      = (const float*)d_in[5];
    const float* Wk      = (const float*)d_in[6];
    const float* Wv      = (const float*)d_in[7];
    const float* bv      = (const float*)d_in[8];
    const float* Wo      = (const float*)d_in[9];
    const float* bo      = (const float*)d_in[10];
    const int*   qpos    = (const int*)d_in[11];
    const int*   kpos    = (const int*)d_in[12];
    float* out = (float*)d_out;

    const int attn_smem = (8704 + 4352 + 4608) * 4;   // 70656 B
    cudaFuncSetAttribute(attn_kernel, cudaFuncAttributeMaxDynamicSharedMemorySize, attn_smem);

    float *pq, *pk, *pv, *pwv;
    cudaGetSymbolAddress((void**)&pq,  g_q);
    cudaGetSymbolAddress((void**)&pk,  g_k);
    cudaGetSymbolAddress((void**)&pv,  g_v);
    cudaGetSymbolAddress((void**)&pwv, g_wv);

    init_invf_kernel<<<1, 32>>>();
    init_cache_kernel<<<(Bb*Hh*Ss*HD/4 + 255)/256, 256>>>((const float4*)k_cache,
                                                          (const float4*)v_cache);

    dim3 gg(Dd/64, Mm/128);   // (16, 32)
    gemm_kernel<1><<<gg, 256>>>(qx,  Wq, bq,      pq,  qpos, nullptr);
    gemm_kernel<1><<<gg, 256>>>(kvx, Wk, nullptr, pk,  kpos, kpos);
    gemm_kernel<1><<<gg, 256>>>(kvx, Wv, bv,      pv,  nullptr, kpos);

    attn_kernel<<<dim3(Ss/128, Bb*Hh), 256, attn_smem>>>(pwv);

    gemm_kernel<0><<<gg, 256>>>(pwv, Wo, bo, out, nullptr, nullptr);
}

// round 13
// speedup vs baseline: 1.0025x; 1.0016x over previous
#include <cuda_runtime.h>
#include <cstdint>
#include <math.h>

#define Bb 2
#define Ss 2048
#define Dd 1024
#define Hh 16
#define HD 64
#define Mm (Bb*Ss)

// Scratch (allocation-free: __device__ globals)
__device__ float g_q[Bb*Hh*Ss*HD];
__device__ float g_k[Bb*Hh*Ss*HD];
__device__ float g_v[Bb*Hh*Ss*HD];
__device__ float g_wv[Bb*Ss*Dd];
__device__ float g_invf[32];

// ---------------------------------------------------------------------------
__device__ __forceinline__ float tf32r(float x) {
    unsigned int u;
    asm("cvt.rna.tf32.f32 %0, %1;" : "=r"(u) : "f"(x));
    return __uint_as_float(u);
}
__device__ __forceinline__ unsigned int tf32u(float x) {
    unsigned int u;
    asm("cvt.rna.tf32.f32 %0, %1;" : "=r"(u) : "f"(x));
    return u;
}

__device__ __forceinline__ void mma_tf32(float* d, const unsigned int* a, const unsigned int* b) {
    asm volatile(
        "mma.sync.aligned.m16n8k8.row.col.f32.tf32.tf32.f32 "
        "{%0,%1,%2,%3}, {%4,%5,%6,%7}, {%8,%9}, {%0,%1,%2,%3};"
        : "+f"(d[0]), "+f"(d[1]), "+f"(d[2]), "+f"(d[3])
        : "r"(a[0]), "r"(a[1]), "r"(a[2]), "r"(a[3]), "r"(b[0]), "r"(b[1]));
}

__device__ __forceinline__ void cp16(unsigned int dst, const void* src) {
    asm volatile("cp.async.ca.shared.global [%0], [%1], 16;\n" :: "r"(dst), "l"(src));
}
__device__ __forceinline__ void cp_commit() {
    asm volatile("cp.async.commit_group;\n");
}
template<int N>
__device__ __forceinline__ void cp_wait() {
    asm volatile("cp.async.wait_group %0;\n" :: "n"(N));
}

// ---------------------------------------------------------------------------
__global__ void init_invf_kernel() {
    int j = threadIdx.x;
    if (j < 32)
        g_invf[j] = (float)exp(-9.210340371976184 * ((double)j / 32.0));
}

__global__ void init_cache_kernel(const float4* __restrict__ kc,
                                  const float4* __restrict__ vc) {
    int i = blockIdx.x * blockDim.x + threadIdx.x;
    ((float4*)g_k)[i] = kc[i];
    ((float4*)g_v)[i] = vc[i];
}

// ---------------------------------------------------------------------------
// tf32 tensor-core GEMM, 3-stage cp.async: C[m][n] = sum_k X[m][k]*W[n][k](+b)
// BM=128, BN=64, BK=16; 256 thr = 8 warps (4Mx2N), warp tile 32x32.
// Smem per stage: As[128][20] + Bs[64][20] (fp32 raw; tf32 cvt at frag load).
// 3 stages = 46080 B, unioned with epilogue Cs[128][68].
// ---------------------------------------------------------------------------
#define GSTG 3840           // floats per stage
#define ASOFF(st,m,k) ((st)*GSTG + (m)*20 + (k))
#define BSOFF(st,n,k) ((st)*GSTG + 2560 + (n)*20 + (k))

template<int MODE>
__global__ void __launch_bounds__(256) gemm_kernel(
    const float* __restrict__ X, const float* __restrict__ W,
    const float* __restrict__ bias, float* __restrict__ out,
    const int* __restrict__ rope_pos, const int* __restrict__ scat_pos)
{
    const int K = Dd;
    __shared__ __align__(16) float sm[3*GSTG];   // 46080 B
    float (*Cs)[68] = (float(*)[68])sm;          // epilogue (after sync)
    unsigned int smb = (unsigned int)__cvta_generic_to_shared(sm);

    const int tid  = threadIdx.x;
    const int warp = tid >> 5, lane = tid & 31;
    const int wy = warp & 3, wx = warp >> 2;
    const int lr = lane >> 2, lc = lane & 3;
    const int m0 = blockIdx.y * 128, n0 = blockIdx.x * 64;

    const float* Xb = X + (size_t)m0 * K;
    const float* Wb = W + (size_t)n0 * K;

    // staging assignment: 768 16B-chunks/stage, 3 per thread
    const int ar0 = tid >> 1;                 // As rows: tid/2 (two chunks each)
    const int ak0 = (tid & 1) * 2;            // chunk cols 0/1 or 2/3
    const int br  = tid >> 2, bk = tid & 3;   // Bs: one chunk

    auto issue = [&](int i) {
        int kt = i * 16, st = i % 3;
        cp16(smb + 4*ASOFF(st, ar0, ak0*4),     Xb + (size_t)ar0 * K + kt + ak0*4);
        cp16(smb + 4*ASOFF(st, ar0, (ak0+1)*4), Xb + (size_t)ar0 * K + kt + (ak0+1)*4);
        cp16(smb + 4*BSOFF(st, br, bk*4),       Wb + (size_t)br  * K + kt + bk*4);
    };

    float acc[2][4][4] = {};

    issue(0); cp_commit();
    issue(1); cp_commit();

    const int NT = K / 16;   // 64
    for (int i = 0; i < NT; i++) {
        cp_wait<1>();
        __syncthreads();
        if (i + 2 < NT) issue(i + 2);
        cp_commit();

        const int cb = i % 3;
#pragma unroll
        for (int kf = 0; kf < 16; kf += 8) {
            unsigned int a[2][4], b[4][2];
#pragma unroll
            for (int mf = 0; mf < 2; mf++) {
                int m = wy*32 + mf*16 + lr;
                a[mf][0] = tf32u(sm[ASOFF(cb, m,   kf+lc)]);
                a[mf][1] = tf32u(sm[ASOFF(cb, m+8, kf+lc)]);
                a[mf][2] = tf32u(sm[ASOFF(cb, m,   kf+4+lc)]);
                a[mf][3] = tf32u(sm[ASOFF(cb, m+8, kf+4+lc)]);
            }
#pragma unroll
            for (int nf = 0; nf < 4; nf++) {
                int n = wx*32 + nf*8 + lr;
                b[nf][0] = tf32u(sm[BSOFF(cb, n, kf+lc)]);
                b[nf][1] = tf32u(sm[BSOFF(cb, n, kf+4+lc)]);
            }
#pragma unroll
            for (int mf = 0; mf < 2; mf++)
#pragma unroll
                for (int nf = 0; nf < 4; nf++)
                    mma_tf32(acc[mf][nf], a[mf], b[nf]);
        }
    }

    if (MODE == 0) {
#pragma unroll
        for (int mf = 0; mf < 2; mf++)
#pragma unroll
            for (int nf = 0; nf < 4; nf++) {
                int mA = m0 + wy*32 + mf*16 + lr;
                int nA = n0 + wx*32 + nf*8 + 2*lc;
                float b0 = bias ? bias[nA]   : 0.f;
                float b1 = bias ? bias[nA+1] : 0.f;
                out[(size_t)mA     * Dd + nA    ] = acc[mf][nf][0] + b0;
                out[(size_t)mA     * Dd + nA + 1] = acc[mf][nf][1] + b1;
                out[(size_t)(mA+8) * Dd + nA    ] = acc[mf][nf][2] + b0;
                out[(size_t)(mA+8) * Dd + nA + 1] = acc[mf][nf][3] + b1;
            }
        return;
    }

    // MODE 1: stage into Cs (overlaps stage buffers -> sync first)
    __syncthreads();
#pragma unroll
    for (int mf = 0; mf < 2; mf++)
#pragma unroll
        for (int nf = 0; nf < 4; nf++) {
            int r = wy*32 + mf*16 + lr;
            int c = wx*32 + nf*8 + 2*lc;
            float b0 = bias ? bias[n0 + c]     : 0.f;
            float b1 = bias ? bias[n0 + c + 1] : 0.f;
            Cs[r  ][c  ] = acc[mf][nf][0] + b0;
            Cs[r  ][c+1] = acc[mf][nf][1] + b1;
            Cs[r+8][c  ] = acc[mf][nf][2] + b0;
            Cs[r+8][c+1] = acc[mf][nf][3] + b1;
        }
    __syncthreads();

    const int tx = tid & 15, ty = tid >> 4;
    const int h = n0 >> 6;
    float invf4[4];
#pragma unroll
    for (int j = 0; j < 4; j++) invf4[j] = g_invf[(tx*4 + j) & 31];

#pragma unroll
    for (int i = 0; i < 8; i++) {
        int row = ty*8 + i;
        int m = m0 + row;
        int b = m >> 11;
        int s = m & 2047;
        int dst = scat_pos ? scat_pos[s] : s;
        float* orow = out + (((size_t)(b*Hh + h)) * Ss + dst) * HD;
        if (rope_pos) {
            float p = (float)rope_pos[s];
#pragma unroll
            for (int j = 0; j < 4; j++) {
                int d = tx*4 + j;
                float x   = Cs[row][d];
                float rot = (d < 32) ? -Cs[row][d+32] : Cs[row][d-32];
                float ang = p * invf4[j];
                orow[d] = x * cosf(ang) + rot * sinf(ang);
            }
        } else {
#pragma unroll
            for (int j = 0; j < 4; j++)
                orow[tx*4+j] = Cs[row][tx*4+j];
        }
    }
}

// ---------------------------------------------------------------------------
// tf32 tensor-core causal flash attention.
// Grid (Ss/128, B*H), 256 thr = 8 warps. Br=128, Bc=64, warp tile 16x64.
// K and V both staged coalesced row-major; pads chosen conflict-free.
// ---------------------------------------------------------------------------
__global__ void __launch_bounds__(256, 1) attn_kernel(float* __restrict__ wv)
{
    extern __shared__ float smf[];
    float (*Qs)[68] = (float(*)[68])smf;                 // also Ps
    float (*Ks)[68] = (float(*)[68])(smf + 8704);        // [kv][d] pad 68
    float (*Vs)[72] = (float(*)[72])(smf + 8704 + 4352); // [kv][d] pad 72

    const int tid  = threadIdx.x;
    const int warp = tid >> 5, lane = tid & 31;
    const int lr = lane >> 2, lc = lane & 3;
    const int bh = blockIdx.y;
    const int qt = (int)gridDim.x - 1 - (int)blockIdx.x; // heavy blocks first
    const int qb = qt * 128;

    const float* Qg = g_q + ((size_t)bh * Ss + qb) * HD;
    const float* Kg = g_k + (size_t)bh * Ss * HD;
    const float* Vg = g_v + (size_t)bh * Ss * HD;

    // stage Q (x 1/8, tf32)
#pragma unroll
    for (int it = 0; it < 8; it++) {
        int idx = tid + it*256;
        int r = idx >> 4, c4 = idx & 15;
        float4 v = *(const float4*)(Qg + (size_t)r*HD + c4*4);
        float4 o4;
        o4.x = tf32r(v.x * 0.125f); o4.y = tf32r(v.y * 0.125f);
        o4.z = tf32r(v.z * 0.125f); o4.w = tf32r(v.w * 0.125f);
        *(float4*)&Qs[r][c4*4] = o4;
    }
    __syncthreads();

    // Q fragments -> registers
    const int mrow = warp*16 + lr;
    unsigned int qa[8][4];
#pragma unroll
    for (int ks = 0; ks < 8; ks++) {
        int d0 = ks*8;
        qa[ks][0] = __float_as_uint(Qs[mrow  ][d0+lc]);
        qa[ks][1] = __float_as_uint(Qs[mrow+8][d0+lc]);
        qa[ks][2] = __float_as_uint(Qs[mrow  ][d0+4+lc]);
        qa[ks][3] = __float_as_uint(Qs[mrow+8][d0+4+lc]);
    }

    float o[8][4] = {};
    float m_i[2] = {-3.0e38f, -3.0e38f};
    float l_i[2] = {0.f, 0.f};

    const int jmax = 2*qt + 1;
    for (int jt = 0; jt <= jmax; jt++) {
        __syncthreads();
        // stage K coalesced [kv][d]
#pragma unroll
        for (int it = 0; it < 4; it++) {
            int idx = tid + it*256;
            int r = idx >> 4, c4 = idx & 15;
            float4 v = *(const float4*)(Kg + (size_t)(jt*64 + r)*HD + c4*4);
            float4 o4;
            o4.x = tf32r(v.x); o4.y = tf32r(v.y);
            o4.z = tf32r(v.z); o4.w = tf32r(v.w);
            *(float4*)&Ks[r][c4*4] = o4;
        }
        // stage V coalesced [kv][d]
#pragma unroll
        for (int it = 0; it < 4; it++) {
            int idx = tid + it*256;
            int r = idx >> 4, c4 = idx & 15;
            float4 v = *(const float4*)(Vg + (size_t)(jt*64 + r)*HD + c4*4);
            float4 o4;
            o4.x = tf32r(v.x); o4.y = tf32r(v.y);
            o4.z = tf32r(v.z); o4.w = tf32r(v.w);
            *(float4*)&Vs[r][c4*4] = o4;
        }
        __syncthreads();

        // S = (Q/8) K^T   (16x64 per warp);  B[n=kv][k=d] col-major = Ks[kv][d]
        float sacc[8][4] = {};
#pragma unroll
        for (int ks = 0; ks < 8; ks++) {
            int d0 = ks*8;
#pragma unroll
            for (int nf = 0; nf < 8; nf++) {
                unsigned int b[2];
                b[0] = __float_as_uint(Ks[nf*8+lr][d0+lc]);
                b[1] = __float_as_uint(Ks[nf*8+lr][d0+4+lc]);
                mma_tf32(sacc[nf], qa[ks], b);
            }
        }

        // causal mask (only the 2 diagonal tiles)
        if (jt >= 2*qt) {
            int row0 = qb + warp*16 + lr;
#pragma unroll
            for (int nf = 0; nf < 8; nf++) {
                int col = jt*64 + nf*8 + 2*lc;
                if (col   > row0)     sacc[nf][0] = -1.0e30f;
                if (col+1 > row0)     sacc[nf][1] = -1.0e30f;
                if (col   > row0+8)   sacc[nf][2] = -1.0e30f;
                if (col+1 > row0+8)   sacc[nf][3] = -1.0e30f;
            }
        }

        // online softmax
        float rmax0 = -3.0e38f, rmax1 = -3.0e38f;
#pragma unroll
        for (int nf = 0; nf < 8; nf++) {
            rmax0 = fmaxf(rmax0, fmaxf(sacc[nf][0], sacc[nf][1]));
            rmax1 = fmaxf(rmax1, fmaxf(sacc[nf][2], sacc[nf][3]));
        }
        rmax0 = fmaxf(rmax0, __shfl_xor_sync(0xffffffffu, rmax0, 1));
        rmax0 = fmaxf(rmax0, __shfl_xor_sync(0xffffffffu, rmax0, 2));
        rmax1 = fmaxf(rmax1, __shfl_xor_sync(0xffffffffu, rmax1, 1));
        rmax1 = fmaxf(rmax1, __shfl_xor_sync(0xffffffffu, rmax1, 2));

        float mn0 = fmaxf(m_i[0], rmax0);
        float mn1 = fmaxf(m_i[1], rmax1);
        float al0 = __expf(m_i[0] - mn0);
        float al1 = __expf(m_i[1] - mn1);
        m_i[0] = mn0; m_i[1] = mn1;

        float ls0 = 0.f, ls1 = 0.f;
#pragma unroll
        for (int nf = 0; nf < 8; nf++) {
            sacc[nf][0] = __expf(sacc[nf][0] - mn0);
            sacc[nf][1] = __expf(sacc[nf][1] - mn0);
            sacc[nf][2] = __expf(sacc[nf][2] - mn1);
            sacc[nf][3] = __expf(sacc[nf][3] - mn1);
            ls0 += sacc[nf][0] + sacc[nf][1];
            ls1 += sacc[nf][2] + sacc[nf][3];
        }
        ls0 += __shfl_xor_sync(0xffffffffu, ls0, 1);
        ls0 += __shfl_xor_sync(0xffffffffu, ls0, 2);
        ls1 += __shfl_xor_sync(0xffffffffu, ls1, 1);
        ls1 += __shfl_xor_sync(0xffffffffu, ls1, 2);
        l_i[0] = l_i[0]*al0 + ls0;
        l_i[1] = l_i[1]*al1 + ls1;

#pragma unroll
        for (int nf = 0; nf < 8; nf++) {
            o[nf][0] *= al0; o[nf][1] *= al0;
            o[nf][2] *= al1; o[nf][3] *= al1;
        }

        // store P (tf32) into Ps (=Qs) rows owned by this warp only
#pragma unroll
        for (int nf = 0; nf < 8; nf++) {
            float2 p0, p1;
            p0.x = tf32r(sacc[nf][0]); p0.y = tf32r(sacc[nf][1]);
            p1.x = tf32r(sacc[nf][2]); p1.y = tf32r(sacc[nf][3]);
            *(float2*)&Qs[mrow  ][nf*8 + 2*lc] = p0;
            *(float2*)&Qs[mrow+8][nf*8 + 2*lc] = p1;
        }
        __syncwarp();

        // O += P V
#pragma unroll
        for (int ks = 0; ks < 8; ks++) {
            int k0 = ks*8;
            unsigned int ap[4];
            ap[0] = __float_as_uint(Qs[mrow  ][k0+lc]);
            ap[1] = __float_as_uint(Qs[mrow+8][k0+lc]);
            ap[2] = __float_as_uint(Qs[mrow  ][k0+4+lc]);
            ap[3] = __float_as_uint(Qs[mrow+8][k0+4+lc]);
#pragma unroll
            for (int nf = 0; nf < 8; nf++) {
                unsigned int b[2];
                b[0] = __float_as_uint(Vs[k0+lc  ][nf*8+lr]);
                b[1] = __float_as_uint(Vs[k0+4+lc][nf*8+lr]);
                mma_tf32(o[nf], ap, b);
            }
        }
    }

    const int b = bh >> 4, h = bh & 15;
    const float inv0 = 1.f / l_i[0];
    const float inv1 = 1.f / l_i[1];
    const int s0 = qb + warp*16 + lr;
    float* row0 = wv + ((size_t)(b*Ss + s0)) * Dd + h*HD;
    float* row1 = row0 + (size_t)8 * Dd;
#pragma unroll
    for (int nf = 0; nf < 8; nf++) {
        float2 w0, w1;
        w0.x = o[nf][0]*inv0; w0.y = o[nf][1]*inv0;
        w1.x = o[nf][2]*inv1; w1.y = o[nf][3]*inv1;
        *(float2*)&row0[nf*8 + 2*lc] = w0;
        *(float2*)&row1[nf*8 + 2*lc] = w1;
    }
}

// ---------------------------------------------------------------------------
extern "C" void kernel_launch(void* const* d_in, const int* in_sizes, int n_in,
                              void* d_out, int out_size)
{
    const float* qx      = (const float*)d_in[0];
    const float* kvx     = (const float*)d_in[1];
    const float* k_cache = (const float*)d_in[2];
    const float* v_cache = (const float*)d_in[3];
    const float* Wq      = (const float*)d_in[4];
    const float* bq      = (const float*)d_in[5];
    const float* Wk      = (const float*)d_in[6];
    const float* Wv      = (const float*)d_in[7];
    const float* bv      = (const float*)d_in[8];
    const float* Wo      = (const float*)d_in[9];
    const float* bo      = (const float*)d_in[10];
    const int*   qpos    = (const int*)d_in[11];
    const int*   kpos    = (const int*)d_in[12];
    float* out = (float*)d_out;

    const int attn_smem = (8704 + 4352 + 4608) * 4;   // 70656 B
    cudaFuncSetAttribute(attn_kernel, cudaFuncAttributeMaxDynamicSharedMemorySize, attn_smem);

    float *pq, *pk, *pv, *pwv;
    cudaGetSymbolAddress((void**)&pq,  g_q);
    cudaGetSymbolAddress((void**)&pk,  g_k);
    cudaGetSymbolAddress((void**)&pv,  g_v);
    cudaGetSymbolAddress((void**)&pwv, g_wv);

    init_invf_kernel<<<1, 32>>>();
    init_cache_kernel<<<(Bb*Hh*Ss*HD/4 + 255)/256, 256>>>((const float4*)k_cache,
                                                          (const float4*)v_cache);

    dim3 gg(Dd/64, Mm/128);   // (16, 32)
    gemm_kernel<1><<<gg, 256>>>(qx,  Wq, bq,      pq,  qpos, nullptr);
    gemm_kernel<1><<<gg, 256>>>(kvx, Wk, nullptr, pk,  kpos, kpos);
    gemm_kernel<1><<<gg, 256>>>(kvx, Wv, bv,      pv,  nullptr, kpos);

    attn_kernel<<<dim3(Ss/128, Bb*Hh), 256, attn_smem>>>(pwv);

    gemm_kernel<0><<<gg, 256>>>(pwv, Wo, bo, out, nullptr, nullptr);
}